// round 1
// baseline (speedup 1.0000x reference)
#include <cuda_runtime.h>
#include <math.h>

#define NROWS 4096
#define DDIM  1024
#define TWO_N 8192
#define BM 64
#define BN 64
#define BK 16

__device__ float g_xn[NROWS * DDIM];      // normalized input
__device__ float g_cat[TWO_N * DDIM];     // normalized [target; hard_negative]
__device__ float g_rowsum[NROWS];         // per-row sum of exp(logit)
__device__ float g_diag[NROWS];           // pos logit at (i,i)

__constant__ float c_temp_inv = 20.0f;    // 1 / 0.05
__constant__ float c_eps = 1e-8f;

// ---------------------------------------------------------------------------
// Kernel A: row-normalize all three matrices; also zero g_rowsum.
// grid = 3*NROWS blocks, 256 threads. Each thread handles 4 floats (float4).
// ---------------------------------------------------------------------------
__global__ void __launch_bounds__(256) normalize_kernel(
    const float* __restrict__ x,
    const float* __restrict__ t,
    const float* __restrict__ h)
{
    int r = blockIdx.x;
    const float* src;
    float* dst;
    if (r < NROWS) {
        src = x + (size_t)r * DDIM;            dst = g_xn + (size_t)r * DDIM;
    } else if (r < 2 * NROWS) {
        src = t + (size_t)(r - NROWS) * DDIM;  dst = g_cat + (size_t)(r - NROWS) * DDIM;
    } else {
        src = h + (size_t)(r - 2 * NROWS) * DDIM;
        dst = g_cat + (size_t)(r - NROWS) * DDIM;   // h occupies cat rows N..2N-1
    }

    int tid = threadIdx.x;
    float4 v = reinterpret_cast<const float4*>(src)[tid];
    float ss = v.x * v.x + v.y * v.y + v.z * v.z + v.w * v.w;

    // block reduce (8 warps)
    #pragma unroll
    for (int o = 16; o > 0; o >>= 1) ss += __shfl_xor_sync(0xffffffffu, ss, o);
    __shared__ float warp_s[8];
    int lane = tid & 31, w = tid >> 5;
    if (lane == 0) warp_s[w] = ss;
    __syncthreads();
    if (w == 0) {
        float s = (lane < 8) ? warp_s[lane] : 0.0f;
        #pragma unroll
        for (int o = 4; o > 0; o >>= 1) s += __shfl_xor_sync(0xffffffffu, s, o);
        if (lane == 0) warp_s[0] = s;
    }
    __syncthreads();

    float inv = 1.0f / fmaxf(sqrtf(warp_s[0]), c_eps);
    v.x *= inv; v.y *= inv; v.z *= inv; v.w *= inv;
    reinterpret_cast<float4*>(dst)[tid] = v;

    if (r < NROWS && tid == 0) g_rowsum[r] = 0.0f;
}

// ---------------------------------------------------------------------------
// Kernel B: fused GEMM (Xn @ Catᵀ) + exp + per-row sum accumulate.
// Tile 64x64, BK=16, 256 threads (16x16), 4x4 micro-tile per thread.
// grid = (TWO_N/BN, NROWS/BM)
// ---------------------------------------------------------------------------
__global__ void __launch_bounds__(256) sim_kernel()
{
    __shared__ float As[BK][BM + 4];
    __shared__ float Bs[BK][BN + 4];

    const int bi = blockIdx.y;
    const int bj = blockIdx.x;
    const int tid = threadIdx.x;
    const int tx = tid & 15;
    const int ty = tid >> 4;

    const float* Ag = g_xn  + (size_t)bi * BM * DDIM;
    const float* Bg = g_cat + (size_t)bj * BN * DDIM;

    float acc[4][4] = {};

    // Each thread loads one float4 of A tile and one of B tile per K-step:
    // 64 rows x 16 cols = 1024 floats = 256 float4
    const int lr = tid >> 2;          // 0..63
    const int lc = (tid & 3) << 2;    // 0,4,8,12

    for (int k0 = 0; k0 < DDIM; k0 += BK) {
        float4 a = *reinterpret_cast<const float4*>(Ag + (size_t)lr * DDIM + k0 + lc);
        float4 b = *reinterpret_cast<const float4*>(Bg + (size_t)lr * DDIM + k0 + lc);
        As[lc + 0][lr] = a.x; As[lc + 1][lr] = a.y; As[lc + 2][lr] = a.z; As[lc + 3][lr] = a.w;
        Bs[lc + 0][lr] = b.x; Bs[lc + 1][lr] = b.y; Bs[lc + 2][lr] = b.z; Bs[lc + 3][lr] = b.w;
        __syncthreads();

        #pragma unroll
        for (int k = 0; k < BK; k++) {
            float4 av = *reinterpret_cast<const float4*>(&As[k][ty * 4]);
            float4 bv = *reinterpret_cast<const float4*>(&Bs[k][tx * 4]);
            float ar[4] = {av.x, av.y, av.z, av.w};
            float br[4] = {bv.x, bv.y, bv.z, bv.w};
            #pragma unroll
            for (int i = 0; i < 4; i++)
                #pragma unroll
                for (int j = 0; j < 4; j++)
                    acc[i][j] = fmaf(ar[i], br[j], acc[i][j]);
        }
        __syncthreads();
    }

    // Epilogue: logits, +1 at hard-neg diagonal, exp, per-row partial sums.
    float rsum[4] = {0.f, 0.f, 0.f, 0.f};
    #pragma unroll
    for (int i = 0; i < 4; i++) {
        int gi = bi * BM + ty * 4 + i;
        #pragma unroll
        for (int j = 0; j < 4; j++) {
            int gj = bj * BN + tx * 4 + j;
            float logit = acc[i][j] * c_temp_inv;
            if (gj == gi + NROWS) logit += 1.0f;   // hard negative weight
            if (gj == gi) g_diag[gi] = logit;      // pos diag (single writer)
            rsum[i] += __expf(logit);
        }
    }

    // Reduce across the 16 tx lanes sharing each row (within a 16-lane half-warp).
    #pragma unroll
    for (int i = 0; i < 4; i++) {
        float v = rsum[i];
        #pragma unroll
        for (int o = 8; o > 0; o >>= 1) v += __shfl_xor_sync(0xffffffffu, v, o);
        if (tx == 0) atomicAdd(&g_rowsum[bi * BM + ty * 4 + i], v);
    }
}

// ---------------------------------------------------------------------------
// Kernel C: loss = mean_i( log(rowsum_i) - diag_i )
// ---------------------------------------------------------------------------
__global__ void __launch_bounds__(1024) loss_kernel(float* __restrict__ out)
{
    int tid = threadIdx.x;
    float s = 0.0f;
    for (int i = tid; i < NROWS; i += 1024)
        s += logf(g_rowsum[i]) - g_diag[i];

    #pragma unroll
    for (int o = 16; o > 0; o >>= 1) s += __shfl_xor_sync(0xffffffffu, s, o);
    __shared__ float warp_s[32];
    int lane = tid & 31, w = tid >> 5;
    if (lane == 0) warp_s[w] = s;
    __syncthreads();
    if (w == 0) {
        float v = (lane < 32) ? warp_s[lane] : 0.0f;
        #pragma unroll
        for (int o = 16; o > 0; o >>= 1) v += __shfl_xor_sync(0xffffffffu, v, o);
        if (lane == 0) out[0] = v / (float)NROWS;
    }
}

// ---------------------------------------------------------------------------
extern "C" void kernel_launch(void* const* d_in, const int* in_sizes, int n_in,
                              void* d_out, int out_size)
{
    const float* x = (const float*)d_in[0];
    const float* t = (const float*)d_in[1];
    const float* h = (const float*)d_in[2];

    normalize_kernel<<<3 * NROWS, 256>>>(x, t, h);

    dim3 grid(TWO_N / BN, NROWS / BM);
    sim_kernel<<<grid, 256>>>();

    loss_kernel<<<1, 1024>>>((float*)d_out);
}

// round 4
// speedup vs baseline: 7.4754x; 7.4754x over previous
#include <cuda_runtime.h>
#include <cuda_bf16.h>
#include <math.h>
#include <stdint.h>

#define NROWS 4096
#define DDIM  1024
#define TWO_N 8192

#define BM 128
#define BN 128
#define BK 32
#define NKB (DDIM / BK)      // 32 k-blocks
#define ROWB 80              // smem bytes per row: 32 bf16 = 64B + 16B pad (conflict-free ldmatrix)
#define BOFF (BM * ROWB)     // B tile offset within a stage
#define STAGE_BYTES ((BM + BN) * ROWB)   // 20480
#define SMEM_TOTAL (3 * STAGE_BYTES)     // 61440

__device__ __nv_bfloat16 g_xnb[NROWS * DDIM];    // normalized input, bf16
__device__ __nv_bfloat16 g_catb[TWO_N * DDIM];   // normalized [target; hard_negative], bf16
__device__ float g_rowsum[NROWS];
__device__ float g_diag[NROWS];

// ---------------------------------------------------------------------------
__device__ __forceinline__ uint32_t smem_u32(const void* p) {
    uint32_t a;
    asm("{ .reg .u64 t; cvta.to.shared.u64 t, %1; cvt.u32.u64 %0, t; }" : "=r"(a) : "l"(p));
    return a;
}
__device__ __forceinline__ void cp16(uint32_t dst, const void* src) {
    asm volatile("cp.async.cg.shared.global [%0], [%1], 16;" :: "r"(dst), "l"(src));
}
__device__ __forceinline__ void ldsm4(uint32_t* r, uint32_t addr) {
    asm volatile("ldmatrix.sync.aligned.m8n8.x4.shared.b16 {%0,%1,%2,%3}, [%4];"
                 : "=r"(r[0]), "=r"(r[1]), "=r"(r[2]), "=r"(r[3]) : "r"(addr));
}
__device__ __forceinline__ void mma16816(float* c, const uint32_t* a, uint32_t b0, uint32_t b1) {
    asm volatile(
        "mma.sync.aligned.m16n8k16.row.col.f32.bf16.bf16.f32 "
        "{%0,%1,%2,%3}, {%4,%5,%6,%7}, {%8,%9}, {%0,%1,%2,%3};"
        : "+f"(c[0]), "+f"(c[1]), "+f"(c[2]), "+f"(c[3])
        : "r"(a[0]), "r"(a[1]), "r"(a[2]), "r"(a[3]), "r"(b0), "r"(b1));
}

// ---------------------------------------------------------------------------
// Kernel A: row-normalize (fp32 math) -> bf16; zero g_rowsum.
// ---------------------------------------------------------------------------
__global__ void __launch_bounds__(256) normalize_kernel(
    const float* __restrict__ x,
    const float* __restrict__ t,
    const float* __restrict__ h)
{
    int r = blockIdx.x;
    const float* src;
    __nv_bfloat16* dst;
    if (r < NROWS) {
        src = x + (size_t)r * DDIM;            dst = g_xnb + (size_t)r * DDIM;
    } else if (r < 2 * NROWS) {
        src = t + (size_t)(r - NROWS) * DDIM;  dst = g_catb + (size_t)(r - NROWS) * DDIM;
    } else {
        src = h + (size_t)(r - 2 * NROWS) * DDIM;
        dst = g_catb + (size_t)(r - NROWS) * DDIM;   // h -> cat rows N..2N-1
    }

    int tid = threadIdx.x;
    float4 v = reinterpret_cast<const float4*>(src)[tid];
    float ss = v.x * v.x + v.y * v.y + v.z * v.z + v.w * v.w;

    #pragma unroll
    for (int o = 16; o > 0; o >>= 1) ss += __shfl_xor_sync(0xffffffffu, ss, o);
    __shared__ float warp_s[8];
    int lane = tid & 31, w = tid >> 5;
    if (lane == 0) warp_s[w] = ss;
    __syncthreads();
    if (w == 0) {
        float s = (lane < 8) ? warp_s[lane] : 0.0f;
        #pragma unroll
        for (int o = 4; o > 0; o >>= 1) s += __shfl_xor_sync(0xffffffffu, s, o);
        if (lane == 0) warp_s[0] = s;
    }
    __syncthreads();

    float inv = 1.0f / fmaxf(sqrtf(warp_s[0]), 1e-8f);
    ushort4 st;
    st.x = __bfloat16_as_ushort(__float2bfloat16_rn(v.x * inv));
    st.y = __bfloat16_as_ushort(__float2bfloat16_rn(v.y * inv));
    st.z = __bfloat16_as_ushort(__float2bfloat16_rn(v.z * inv));
    st.w = __bfloat16_as_ushort(__float2bfloat16_rn(v.w * inv));
    reinterpret_cast<ushort4*>(dst)[tid] = st;

    if (r < NROWS && tid == 0) g_rowsum[r] = 0.0f;
}

// ---------------------------------------------------------------------------
// Kernel B: bf16 HMMA GEMM (Xn @ Catᵀ) 128x128 tile + fused exp/rowsum.
// 256 threads = 8 warps (2 x 4); warp tile 64x32; mma m16n8k16.
// grid = (TWO_N/BN, NROWS/BM) = (64, 32)
// ---------------------------------------------------------------------------
__device__ __forceinline__ void load_stage(uint32_t sstage, int bi, int bj, int k0, int tid)
{
    #pragma unroll
    for (int t = 0; t < 4; t++) {
        int idx = tid + t * 256;            // 0..1023
        int r = idx >> 2, c = idx & 3;      // row 0..255, 16B chunk 0..3
        if (r < BM) {
            const void* gp = g_xnb + (size_t)(bi * BM + r) * DDIM + k0 + c * 8;
            cp16(sstage + (uint32_t)(r * ROWB + c * 16), gp);
        } else {
            int r2 = r - BM;
            const void* gp = g_catb + (size_t)(bj * BN + r2) * DDIM + k0 + c * 8;
            cp16(sstage + (uint32_t)(BOFF + r2 * ROWB + c * 16), gp);
        }
    }
    asm volatile("cp.async.commit_group;" ::: "memory");
}

__global__ void __launch_bounds__(256) sim_kernel()
{
    extern __shared__ char smem[];
    const uint32_t sb = smem_u32(smem);
    const int tid = threadIdx.x;
    const int lane = tid & 31;
    const int w = tid >> 5;
    const int wm = w >> 2;       // 0..1  -> rows [wm*64, +64)
    const int wn = w & 3;        // 0..3  -> cols [wn*32, +32)
    const int bi = blockIdx.y, bj = blockIdx.x;

    float acc[4][4][4];
    #pragma unroll
    for (int i = 0; i < 4; i++)
        #pragma unroll
        for (int j = 0; j < 4; j++)
            #pragma unroll
            for (int k = 0; k < 4; k++) acc[i][j][k] = 0.0f;

    // per-lane ldmatrix base addresses (stage offset added per iteration)
    const uint32_t aBase = sb + (uint32_t)((wm * 64 + (lane & 15)) * ROWB + ((lane >> 4) << 4));
    const uint32_t bBase = sb + (uint32_t)(BOFF
                          + (wn * 32 + (lane & 7) + ((lane >> 4) << 3)) * ROWB
                          + (((lane >> 3) & 1) << 4));

    load_stage(sb + 0 * STAGE_BYTES, bi, bj, 0 * BK, tid);
    load_stage(sb + 1 * STAGE_BYTES, bi, bj, 1 * BK, tid);

    for (int kb = 0; kb < NKB; kb++) {
        if (kb == NKB - 1) asm volatile("cp.async.wait_group 0;" ::: "memory");
        else               asm volatile("cp.async.wait_group 1;" ::: "memory");
        __syncthreads();

        if (kb + 2 < NKB)
            load_stage(sb + (uint32_t)(((kb + 2) % 3) * STAGE_BYTES), bi, bj, (kb + 2) * BK, tid);

        const uint32_t so = (uint32_t)((kb % 3) * STAGE_BYTES);
        #pragma unroll
        for (int kk = 0; kk < 2; kk++) {         // two k16 steps per BK=32
            uint32_t a[4][4], b[2][4];
            #pragma unroll
            for (int mt = 0; mt < 4; mt++)
                ldsm4(a[mt], aBase + so + (uint32_t)(mt * 16 * ROWB + kk * 32));
            #pragma unroll
            for (int nt2 = 0; nt2 < 2; nt2++)
                ldsm4(b[nt2], bBase + so + (uint32_t)(nt2 * 16 * ROWB + kk * 32));
            #pragma unroll
            for (int mt = 0; mt < 4; mt++) {
                #pragma unroll
                for (int nt = 0; nt < 4; nt++) {
                    const uint32_t* bp = &b[nt >> 1][(nt & 1) * 2];
                    mma16816(acc[mt][nt], a[mt], bp[0], bp[1]);
                }
            }
        }
        __syncthreads();   // before this buffer gets overwritten
    }

    // Epilogue: logits, hard-neg diag +1, exp, per-row sums.
    #pragma unroll
    for (int mt = 0; mt < 4; mt++) {
        const int gi0 = bi * BM + wm * 64 + mt * 16 + (lane >> 2);
        const int gi1 = gi0 + 8;
        float rs0 = 0.0f, rs1 = 0.0f;
        #pragma unroll
        for (int nt = 0; nt < 4; nt++) {
            const int gj = bj * BN + wn * 32 + nt * 8 + ((lane & 3) << 1);
            float l0 = acc[mt][nt][0] * 20.0f;
            float l1 = acc[mt][nt][1] * 20.0f;
            float l2 = acc[mt][nt][2] * 20.0f;
            float l3 = acc[mt][nt][3] * 20.0f;
            if (gj     == gi0 + NROWS) l0 += 1.0f;
            if (gj + 1 == gi0 + NROWS) l1 += 1.0f;
            if (gj     == gi1 + NROWS) l2 += 1.0f;
            if (gj + 1 == gi1 + NROWS) l3 += 1.0f;
            if (gj     == gi0) g_diag[gi0] = l0;
            if (gj + 1 == gi0) g_diag[gi0] = l1;
            if (gj     == gi1) g_diag[gi1] = l2;
            if (gj + 1 == gi1) g_diag[gi1] = l3;
            rs0 += __expf(l0) + __expf(l1);
            rs1 += __expf(l2) + __expf(l3);
        }
        rs0 += __shfl_xor_sync(0xffffffffu, rs0, 1);
        rs0 += __shfl_xor_sync(0xffffffffu, rs0, 2);
        rs1 += __shfl_xor_sync(0xffffffffu, rs1, 1);
        rs1 += __shfl_xor_sync(0xffffffffu, rs1, 2);
        if ((lane & 3) == 0) {
            atomicAdd(&g_rowsum[gi0], rs0);
            atomicAdd(&g_rowsum[gi1], rs1);
        }
    }
}

// ---------------------------------------------------------------------------
// Kernel C: loss = mean_i( log(rowsum_i) - diag_i )
// ---------------------------------------------------------------------------
__global__ void __launch_bounds__(1024) loss_kernel(float* __restrict__ out)
{
    int tid = threadIdx.x;
    float s = 0.0f;
    for (int i = tid; i < NROWS; i += 1024)
        s += logf(g_rowsum[i]) - g_diag[i];

    #pragma unroll
    for (int o = 16; o > 0; o >>= 1) s += __shfl_xor_sync(0xffffffffu, s, o);
    __shared__ float warp_s[32];
    int lane = tid & 31, w = tid >> 5;
    if (lane == 0) warp_s[w] = s;
    __syncthreads();
    if (w == 0) {
        float v = warp_s[lane];
        #pragma unroll
        for (int o = 16; o > 0; o >>= 1) v += __shfl_xor_sync(0xffffffffu, v, o);
        if (lane == 0) out[0] = v / (float)NROWS;
    }
}

// ---------------------------------------------------------------------------
extern "C" void kernel_launch(void* const* d_in, const int* in_sizes, int n_in,
                              void* d_out, int out_size)
{
    const float* x = (const float*)d_in[0];
    const float* t = (const float*)d_in[1];
    const float* h = (const float*)d_in[2];

    cudaFuncSetAttribute(sim_kernel, cudaFuncAttributeMaxDynamicSharedMemorySize, SMEM_TOTAL);

    normalize_kernel<<<3 * NROWS, 256>>>(x, t, h);

    dim3 grid(TWO_N / BN, NROWS / BM);   // (64, 32)
    sim_kernel<<<grid, 256, SMEM_TOTAL>>>();

    loss_kernel<<<1, 1024>>>((float*)d_out);
}

// round 7
// speedup vs baseline: 7.9654x; 1.0656x over previous
#include <cuda_runtime.h>
#include <cuda_bf16.h>
#include <math.h>
#include <stdint.h>

#define NROWS 4096
#define DDIM  1024
#define TWO_N 8192

#define BM 128
#define BN 256
#define BK 64
#define NKB (DDIM / BK)          // 16 k-blocks
#define ROWB 144                 // 128B data + 16B pad -> conflict-free ldmatrix
#define BOFF (BM * ROWB)         // B tile offset within a stage (18432)
#define STAGE_BYTES ((BM + BN) * ROWB)   // 55296
#define SMEM_TOTAL (3 * STAGE_BYTES)     // 165888

__device__ __nv_bfloat16 g_xnb[NROWS * DDIM];    // normalized input, bf16
__device__ __nv_bfloat16 g_catb[TWO_N * DDIM];   // normalized [target; hard_negative], bf16
__device__ float g_rowsum[NROWS];
__device__ float g_diag[NROWS];

// ---------------------------------------------------------------------------
__device__ __forceinline__ uint32_t smem_u32(const void* p) {
    uint32_t a;
    asm("{ .reg .u64 t; cvta.to.shared.u64 t, %1; cvt.u32.u64 %0, t; }" : "=r"(a) : "l"(p));
    return a;
}
__device__ __forceinline__ void cp16(uint32_t dst, const void* src) {
    asm volatile("cp.async.cg.shared.global [%0], [%1], 16;" :: "r"(dst), "l"(src));
}
__device__ __forceinline__ void ldsm4(uint32_t* r, uint32_t addr) {
    asm volatile("ldmatrix.sync.aligned.m8n8.x4.shared.b16 {%0,%1,%2,%3}, [%4];"
                 : "=r"(r[0]), "=r"(r[1]), "=r"(r[2]), "=r"(r[3]) : "r"(addr));
}
__device__ __forceinline__ void mma16816(float* c, const uint32_t* a, uint32_t b0, uint32_t b1) {
    asm volatile(
        "mma.sync.aligned.m16n8k16.row.col.f32.bf16.bf16.f32 "
        "{%0,%1,%2,%3}, {%4,%5,%6,%7}, {%8,%9}, {%0,%1,%2,%3};"
        : "+f"(c[0]), "+f"(c[1]), "+f"(c[2]), "+f"(c[3])
        : "r"(a[0]), "r"(a[1]), "r"(a[2]), "r"(a[3]), "r"(b0), "r"(b1));
}

// ---------------------------------------------------------------------------
// Kernel A: row-normalize (fp32 math) -> bf16; zero g_rowsum.
// ---------------------------------------------------------------------------
__global__ void __launch_bounds__(256) normalize_kernel(
    const float* __restrict__ x,
    const float* __restrict__ t,
    const float* __restrict__ h)
{
    int r = blockIdx.x;
    const float* src;
    __nv_bfloat16* dst;
    if (r < NROWS) {
        src = x + (size_t)r * DDIM;            dst = g_xnb + (size_t)r * DDIM;
    } else if (r < 2 * NROWS) {
        src = t + (size_t)(r - NROWS) * DDIM;  dst = g_catb + (size_t)(r - NROWS) * DDIM;
    } else {
        src = h + (size_t)(r - 2 * NROWS) * DDIM;
        dst = g_catb + (size_t)(r - NROWS) * DDIM;   // h -> cat rows N..2N-1
    }

    int tid = threadIdx.x;
    float4 v = reinterpret_cast<const float4*>(src)[tid];
    float ss = v.x * v.x + v.y * v.y + v.z * v.z + v.w * v.w;

    #pragma unroll
    for (int o = 16; o > 0; o >>= 1) ss += __shfl_xor_sync(0xffffffffu, ss, o);
    __shared__ float warp_s[8];
    int lane = tid & 31, w = tid >> 5;
    if (lane == 0) warp_s[w] = ss;
    __syncthreads();
    if (w == 0) {
        float s = (lane < 8) ? warp_s[lane] : 0.0f;
        #pragma unroll
        for (int o = 4; o > 0; o >>= 1) s += __shfl_xor_sync(0xffffffffu, s, o);
        if (lane == 0) warp_s[0] = s;
    }
    __syncthreads();

    float inv = 1.0f / fmaxf(sqrtf(warp_s[0]), 1e-8f);
    ushort4 st;
    st.x = __bfloat16_as_ushort(__float2bfloat16_rn(v.x * inv));
    st.y = __bfloat16_as_ushort(__float2bfloat16_rn(v.y * inv));
    st.z = __bfloat16_as_ushort(__float2bfloat16_rn(v.z * inv));
    st.w = __bfloat16_as_ushort(__float2bfloat16_rn(v.w * inv));
    reinterpret_cast<ushort4*>(dst)[tid] = st;

    if (r < NROWS && tid == 0) g_rowsum[r] = 0.0f;
}

// ---------------------------------------------------------------------------
// Kernel B: bf16 HMMA GEMM (Xn @ Catᵀ) 128x256 tile + fused exp/rowsum.
// 256 threads = 8 warps (2 x 4); warp tile 64x64; mma m16n8k16; BK=64.
// 3-stage cp.async ring, prefetch distance 2 (NEVER equal to stage count!),
// one __syncthreads per K-iteration.
// grid = (TWO_N/BN, NROWS/BM) = (32, 32)
// ---------------------------------------------------------------------------
__device__ __forceinline__ void load_stage(uint32_t sstage, int bi, int bj, int k0, int tid)
{
    #pragma unroll
    for (int t = 0; t < 12; t++) {
        int idx = tid + t * 256;            // 0..3071
        int r = idx >> 3, c = idx & 7;      // row 0..383, 16B chunk 0..7
        if (r < BM) {
            const void* gp = g_xnb + (size_t)(bi * BM + r) * DDIM + k0 + c * 8;
            cp16(sstage + (uint32_t)(r * ROWB + c * 16), gp);
        } else {
            int r2 = r - BM;
            const void* gp = g_catb + (size_t)(bj * BN + r2) * DDIM + k0 + c * 8;
            cp16(sstage + (uint32_t)(BOFF + r2 * ROWB + c * 16), gp);
        }
    }
    asm volatile("cp.async.commit_group;" ::: "memory");
}

__global__ void __launch_bounds__(256, 1) sim_kernel()
{
    extern __shared__ char smem[];
    const uint32_t sb = smem_u32(smem);
    const int tid = threadIdx.x;
    const int lane = tid & 31;
    const int w = tid >> 5;
    const int wm = w >> 2;       // 0..1 -> rows [wm*64, +64)
    const int wn = w & 3;        // 0..3 -> cols [wn*64, +64)
    const int bi = blockIdx.y, bj = blockIdx.x;

    float acc[4][8][4];
    #pragma unroll
    for (int i = 0; i < 4; i++)
        #pragma unroll
        for (int j = 0; j < 8; j++)
            #pragma unroll
            for (int k = 0; k < 4; k++) acc[i][j][k] = 0.0f;

    // per-lane ldmatrix base addresses (stage offset added per iteration)
    const uint32_t aBase = sb + (uint32_t)((wm * 64 + (lane & 15)) * ROWB + ((lane >> 4) << 4));
    const uint32_t bBase = sb + (uint32_t)(BOFF
                          + (wn * 64 + (lane & 7) + ((lane >> 4) << 3)) * ROWB
                          + (((lane >> 3) & 1) << 4));

    load_stage(sb + 0 * STAGE_BYTES, bi, bj, 0 * BK, tid);
    load_stage(sb + 1 * STAGE_BYTES, bi, bj, 1 * BK, tid);

    for (int kb = 0; kb < NKB; kb++) {
        // stage kb complete; at most stage kb+1 still in flight
        if (kb < NKB - 1) asm volatile("cp.async.wait_group 1;" ::: "memory");
        else              asm volatile("cp.async.wait_group 0;" ::: "memory");
        __syncthreads();   // stage kb visible; also fences iter kb-1 reads of buffer (kb+2)%3

        if (kb + 2 < NKB)
            load_stage(sb + (uint32_t)(((kb + 2) % 3) * STAGE_BYTES), bi, bj, (kb + 2) * BK, tid);

        const uint32_t so = (uint32_t)((kb % 3) * STAGE_BYTES);
        #pragma unroll
        for (int kk = 0; kk < 4; kk++) {        // four k16 steps per BK=64
            uint32_t a[4][4], b[4][4];
            #pragma unroll
            for (int mt = 0; mt < 4; mt++)
                ldsm4(a[mt], aBase + so + (uint32_t)(mt * 16 * ROWB + kk * 32));
            #pragma unroll
            for (int g = 0; g < 4; g++)
                ldsm4(b[g], bBase + so + (uint32_t)(g * 16 * ROWB + kk * 32));
            #pragma unroll
            for (int mt = 0; mt < 4; mt++) {
                #pragma unroll
                for (int nt = 0; nt < 8; nt++) {
                    const uint32_t* bp = &b[nt >> 1][(nt & 1) * 2];
                    mma16816(acc[mt][nt], a[mt], bp[0], bp[1]);
                }
            }
        }
    }

    // Epilogue: logits, hard-neg diag +1, exp, per-row sums.
    #pragma unroll
    for (int mt = 0; mt < 4; mt++) {
        const int gi0 = bi * BM + wm * 64 + mt * 16 + (lane >> 2);
        const int gi1 = gi0 + 8;
        float rs0 = 0.0f, rs1 = 0.0f;
        #pragma unroll
        for (int nt = 0; nt < 8; nt++) {
            const int gj = bj * BN + wn * 64 + nt * 8 + ((lane & 3) << 1);
            float l0 = acc[mt][nt][0] * 20.0f;
            float l1 = acc[mt][nt][1] * 20.0f;
            float l2 = acc[mt][nt][2] * 20.0f;
            float l3 = acc[mt][nt][3] * 20.0f;
            if (gj     == gi0 + NROWS) l0 += 1.0f;
            if (gj + 1 == gi0 + NROWS) l1 += 1.0f;
            if (gj     == gi1 + NROWS) l2 += 1.0f;
            if (gj + 1 == gi1 + NROWS) l3 += 1.0f;
            if (gj     == gi0) g_diag[gi0] = l0;
            if (gj + 1 == gi0) g_diag[gi0] = l1;
            if (gj     == gi1) g_diag[gi1] = l2;
            if (gj + 1 == gi1) g_diag[gi1] = l3;
            rs0 += __expf(l0) + __expf(l1);
            rs1 += __expf(l2) + __expf(l3);
        }
        rs0 += __shfl_xor_sync(0xffffffffu, rs0, 1);
        rs0 += __shfl_xor_sync(0xffffffffu, rs0, 2);
        rs1 += __shfl_xor_sync(0xffffffffu, rs1, 1);
        rs1 += __shfl_xor_sync(0xffffffffu, rs1, 2);
        if ((lane & 3) == 0) {
            atomicAdd(&g_rowsum[gi0], rs0);
            atomicAdd(&g_rowsum[gi1], rs1);
        }
    }
}

// ---------------------------------------------------------------------------
// Kernel C: loss = mean_i( log(rowsum_i) - diag_i )
// ---------------------------------------------------------------------------
__global__ void __launch_bounds__(1024) loss_kernel(float* __restrict__ out)
{
    int tid = threadIdx.x;
    float s = 0.0f;
    for (int i = tid; i < NROWS; i += 1024)
        s += logf(g_rowsum[i]) - g_diag[i];

    #pragma unroll
    for (int o = 16; o > 0; o >>= 1) s += __shfl_xor_sync(0xffffffffu, s, o);
    __shared__ float warp_s[32];
    int lane = tid & 31, w = tid >> 5;
    if (lane == 0) warp_s[w] = s;
    __syncthreads();
    if (w == 0) {
        float v = warp_s[lane];
        #pragma unroll
        for (int o = 16; o > 0; o >>= 1) v += __shfl_xor_sync(0xffffffffu, v, o);
        if (lane == 0) out[0] = v / (float)NROWS;
    }
}

// ---------------------------------------------------------------------------
extern "C" void kernel_launch(void* const* d_in, const int* in_sizes, int n_in,
                              void* d_out, int out_size)
{
    const float* x = (const float*)d_in[0];
    const float* t = (const float*)d_in[1];
    const float* h = (const float*)d_in[2];

    cudaFuncSetAttribute(sim_kernel, cudaFuncAttributeMaxDynamicSharedMemorySize, SMEM_TOTAL);

    normalize_kernel<<<3 * NROWS, 256>>>(x, t, h);

    dim3 grid(TWO_N / BN, NROWS / BM);   // (32, 32)
    sim_kernel<<<grid, 256, SMEM_TOTAL>>>();

    loss_kernel<<<1, 1024>>>((float*)d_out);
}

// round 8
// speedup vs baseline: 8.0281x; 1.0079x over previous
#include <cuda_runtime.h>
#include <cuda_bf16.h>
#include <cuda_fp8.h>
#include <math.h>
#include <stdint.h>

#define NROWS 4096
#define DDIM  1024
#define TWO_N 8192

#define BM 128
#define BN 256
#define BK 64                    // fp8 elements per stage
#define NKB (DDIM / BK)          // 16 k-blocks
#define ROWB 80                  // 64B data + 16B pad -> conflict-free ldmatrix
#define BOFF (BM * ROWB)         // B tile offset within a stage (10240)
#define STAGE_BYTES ((BM + BN) * ROWB)   // 30720
#define SMEM_TOTAL (3 * STAGE_BYTES)     // 92160

// quantization scale: store e4m3(x * 16), logits scaled by 20/(16*16)
#define QSCALE 16.0f
#define LOGIT_SCALE (20.0f / 256.0f)

__device__ uint8_t g_x8[NROWS * DDIM];     // normalized input, e4m3 (x16)
__device__ uint8_t g_cat8[TWO_N * DDIM];   // normalized [target; hard_negative], e4m3 (x16)
__device__ float g_rowsum[NROWS];
__device__ float g_diag[NROWS];

// ---------------------------------------------------------------------------
__device__ __forceinline__ uint32_t smem_u32(const void* p) {
    uint32_t a;
    asm("{ .reg .u64 t; cvta.to.shared.u64 t, %1; cvt.u32.u64 %0, t; }" : "=r"(a) : "l"(p));
    return a;
}
__device__ __forceinline__ void cp16(uint32_t dst, const void* src) {
    asm volatile("cp.async.cg.shared.global [%0], [%1], 16;" :: "r"(dst), "l"(src));
}
__device__ __forceinline__ void ldsm4(uint32_t* r, uint32_t addr) {
    asm volatile("ldmatrix.sync.aligned.m8n8.x4.shared.b16 {%0,%1,%2,%3}, [%4];"
                 : "=r"(r[0]), "=r"(r[1]), "=r"(r[2]), "=r"(r[3]) : "r"(addr));
}
__device__ __forceinline__ void mma_fp8(float* c, const uint32_t* a, uint32_t b0, uint32_t b1) {
    asm volatile(
        "mma.sync.aligned.m16n8k32.row.col.f32.e4m3.e4m3.f32 "
        "{%0,%1,%2,%3}, {%4,%5,%6,%7}, {%8,%9}, {%0,%1,%2,%3};"
        : "+f"(c[0]), "+f"(c[1]), "+f"(c[2]), "+f"(c[3])
        : "r"(a[0]), "r"(a[1]), "r"(a[2]), "r"(a[3]), "r"(b0), "r"(b1));
}

// ---------------------------------------------------------------------------
// Kernel A: row-normalize (fp32 math) -> e4m3 (scaled x16); zero g_rowsum.
// ---------------------------------------------------------------------------
__global__ void __launch_bounds__(256) normalize_kernel(
    const float* __restrict__ x,
    const float* __restrict__ t,
    const float* __restrict__ h)
{
    int r = blockIdx.x;
    const float* src;
    uint8_t* dst;
    if (r < NROWS) {
        src = x + (size_t)r * DDIM;            dst = g_x8 + (size_t)r * DDIM;
    } else if (r < 2 * NROWS) {
        src = t + (size_t)(r - NROWS) * DDIM;  dst = g_cat8 + (size_t)(r - NROWS) * DDIM;
    } else {
        src = h + (size_t)(r - 2 * NROWS) * DDIM;
        dst = g_cat8 + (size_t)(r - NROWS) * DDIM;   // h -> cat rows N..2N-1
    }

    int tid = threadIdx.x;
    float4 v = reinterpret_cast<const float4*>(src)[tid];
    float ss = v.x * v.x + v.y * v.y + v.z * v.z + v.w * v.w;

    #pragma unroll
    for (int o = 16; o > 0; o >>= 1) ss += __shfl_xor_sync(0xffffffffu, ss, o);
    __shared__ float warp_s[8];
    int lane = tid & 31, w = tid >> 5;
    if (lane == 0) warp_s[w] = ss;
    __syncthreads();
    if (w == 0) {
        float s = (lane < 8) ? warp_s[lane] : 0.0f;
        #pragma unroll
        for (int o = 4; o > 0; o >>= 1) s += __shfl_xor_sync(0xffffffffu, s, o);
        if (lane == 0) warp_s[0] = s;
    }
    __syncthreads();

    float inv = QSCALE / fmaxf(sqrtf(warp_s[0]), 1e-8f);
    __nv_fp8x4_e4m3 q(make_float4(v.x * inv, v.y * inv, v.z * inv, v.w * inv));
    reinterpret_cast<uint32_t*>(dst)[tid] = q.__x;

    if (r < NROWS && tid == 0) g_rowsum[r] = 0.0f;
}

// ---------------------------------------------------------------------------
// Kernel B: e4m3 HMMA GEMM (Xq @ Catqᵀ) 128x256 tile + fused exp/rowsum.
// 256 threads = 8 warps (2 x 4); warp tile 64x64; mma m16n8k32; BK=64 fp8.
// 3-stage cp.async ring, prefetch distance 2, one __syncthreads per iter.
// grid = (TWO_N/BN, NROWS/BM) = (32, 32)
// ---------------------------------------------------------------------------
__device__ __forceinline__ void load_stage(uint32_t sstage, int bi, int bj, int k0, int tid)
{
    #pragma unroll
    for (int t = 0; t < 6; t++) {
        int idx = tid + t * 256;            // 0..1535
        int r = idx >> 2, c = idx & 3;      // row 0..383, 16B chunk 0..3
        if (r < BM) {
            const void* gp = g_x8 + (size_t)(bi * BM + r) * DDIM + k0 + c * 16;
            cp16(sstage + (uint32_t)(r * ROWB + c * 16), gp);
        } else {
            int r2 = r - BM;
            const void* gp = g_cat8 + (size_t)(bj * BN + r2) * DDIM + k0 + c * 16;
            cp16(sstage + (uint32_t)(BOFF + r2 * ROWB + c * 16), gp);
        }
    }
    asm volatile("cp.async.commit_group;" ::: "memory");
}

__global__ void __launch_bounds__(256, 1) sim_kernel()
{
    extern __shared__ char smem[];
    const uint32_t sb = smem_u32(smem);
    const int tid = threadIdx.x;
    const int lane = tid & 31;
    const int w = tid >> 5;
    const int wm = w >> 2;       // 0..1 -> rows [wm*64, +64)
    const int wn = w & 3;        // 0..3 -> cols [wn*64, +64)
    const int bi = blockIdx.y, bj = blockIdx.x;

    float acc[4][8][4];
    #pragma unroll
    for (int i = 0; i < 4; i++)
        #pragma unroll
        for (int j = 0; j < 8; j++)
            #pragma unroll
            for (int k = 0; k < 4; k++) acc[i][j][k] = 0.0f;

    // per-lane ldmatrix base addresses (b16 view: 1 b16 = 2 fp8)
    const uint32_t aBase = sb + (uint32_t)((wm * 64 + (lane & 15)) * ROWB + ((lane >> 4) << 4));
    const uint32_t bBase = sb + (uint32_t)(BOFF
                          + (wn * 64 + (lane & 7) + ((lane >> 4) << 3)) * ROWB
                          + (((lane >> 3) & 1) << 4));

    load_stage(sb + 0 * STAGE_BYTES, bi, bj, 0 * BK, tid);
    load_stage(sb + 1 * STAGE_BYTES, bi, bj, 1 * BK, tid);

    for (int kb = 0; kb < NKB; kb++) {
        // stage kb complete; at most stage kb+1 still in flight
        if (kb < NKB - 1) asm volatile("cp.async.wait_group 1;" ::: "memory");
        else              asm volatile("cp.async.wait_group 0;" ::: "memory");
        __syncthreads();   // stage kb visible; fences iter kb-1 reads of buffer (kb+2)%3

        if (kb + 2 < NKB)
            load_stage(sb + (uint32_t)(((kb + 2) % 3) * STAGE_BYTES), bi, bj, (kb + 2) * BK, tid);

        const uint32_t so = (uint32_t)((kb % 3) * STAGE_BYTES);
        #pragma unroll
        for (int kk = 0; kk < 2; kk++) {        // two k32 steps per BK=64 fp8
            uint32_t a[4][4], b[4][4];
            #pragma unroll
            for (int mt = 0; mt < 4; mt++)
                ldsm4(a[mt], aBase + so + (uint32_t)(mt * 16 * ROWB + kk * 32));
            #pragma unroll
            for (int g = 0; g < 4; g++)
                ldsm4(b[g], bBase + so + (uint32_t)(g * 16 * ROWB + kk * 32));
            #pragma unroll
            for (int mt = 0; mt < 4; mt++) {
                #pragma unroll
                for (int nt = 0; nt < 8; nt++) {
                    const uint32_t* bp = &b[nt >> 1][(nt & 1) * 2];
                    mma_fp8(acc[mt][nt], a[mt], bp[0], bp[1]);
                }
            }
        }
    }

    // Epilogue: logits, hard-neg diag +1, exp, per-row sums.
    #pragma unroll
    for (int mt = 0; mt < 4; mt++) {
        const int gi0 = bi * BM + wm * 64 + mt * 16 + (lane >> 2);
        const int gi1 = gi0 + 8;
        float rs0 = 0.0f, rs1 = 0.0f;
        #pragma unroll
        for (int nt = 0; nt < 8; nt++) {
            const int gj = bj * BN + wn * 64 + nt * 8 + ((lane & 3) << 1);
            float l0 = acc[mt][nt][0] * LOGIT_SCALE;
            float l1 = acc[mt][nt][1] * LOGIT_SCALE;
            float l2 = acc[mt][nt][2] * LOGIT_SCALE;
            float l3 = acc[mt][nt][3] * LOGIT_SCALE;
            if (gj     == gi0 + NROWS) l0 += 1.0f;
            if (gj + 1 == gi0 + NROWS) l1 += 1.0f;
            if (gj     == gi1 + NROWS) l2 += 1.0f;
            if (gj + 1 == gi1 + NROWS) l3 += 1.0f;
            if (gj     == gi0) g_diag[gi0] = l0;
            if (gj + 1 == gi0) g_diag[gi0] = l1;
            if (gj     == gi1) g_diag[gi1] = l2;
            if (gj + 1 == gi1) g_diag[gi1] = l3;
            rs0 += __expf(l0) + __expf(l1);
            rs1 += __expf(l2) + __expf(l3);
        }
        rs0 += __shfl_xor_sync(0xffffffffu, rs0, 1);
        rs0 += __shfl_xor_sync(0xffffffffu, rs0, 2);
        rs1 += __shfl_xor_sync(0xffffffffu, rs1, 1);
        rs1 += __shfl_xor_sync(0xffffffffu, rs1, 2);
        if ((lane & 3) == 0) {
            atomicAdd(&g_rowsum[gi0], rs0);
            atomicAdd(&g_rowsum[gi1], rs1);
        }
    }
}

// ---------------------------------------------------------------------------
// Kernel C: loss = mean_i( log(rowsum_i) - diag_i )
// ---------------------------------------------------------------------------
__global__ void __launch_bounds__(1024) loss_kernel(float* __restrict__ out)
{
    int tid = threadIdx.x;
    float s = 0.0f;
    for (int i = tid; i < NROWS; i += 1024)
        s += logf(g_rowsum[i]) - g_diag[i];

    #pragma unroll
    for (int o = 16; o > 0; o >>= 1) s += __shfl_xor_sync(0xffffffffu, s, o);
    __shared__ float warp_s[32];
    int lane = tid & 31, w = tid >> 5;
    if (lane == 0) warp_s[w] = s;
    __syncthreads();
    if (w == 0) {
        float v = warp_s[lane];
        #pragma unroll
        for (int o = 16; o > 0; o >>= 1) v += __shfl_xor_sync(0xffffffffu, v, o);
        if (lane == 0) out[0] = v / (float)NROWS;
    }
}

// ---------------------------------------------------------------------------
extern "C" void kernel_launch(void* const* d_in, const int* in_sizes, int n_in,
                              void* d_out, int out_size)
{
    const float* x = (const float*)d_in[0];
    const float* t = (const float*)d_in[1];
    const float* h = (const float*)d_in[2];

    cudaFuncSetAttribute(sim_kernel, cudaFuncAttributeMaxDynamicSharedMemorySize, SMEM_TOTAL);

    normalize_kernel<<<3 * NROWS, 256>>>(x, t, h);

    dim3 grid(TWO_N / BN, NROWS / BM);   // (32, 32)
    sim_kernel<<<grid, 256, SMEM_TOTAL>>>();

    loss_kernel<<<1, 1024>>>((float*)d_out);
}